// round 1
// baseline (speedup 1.0000x reference)
#include <cuda_runtime.h>

// Problem constants
#define NB 65536
#define NL 1024

// ---------------- device scratch (no allocations allowed) ----------------
// per-row partials: {wave_sq_sum, S1/S2 (raw energy), row_max, pad}
__device__ float4 g_scr[NB];
__device__ double g_acc[3];   // [0]=wave sum, [1]=cls nll sum, [2]=penalty sum
__device__ int    g_cnt;      // n_valid labels
__device__ int    g_maxo;     // global max, ordered-int encoding

__device__ __forceinline__ int   f2o(float f){ int i=__float_as_int(f); return i>=0 ? i : (i^0x7FFFFFFF); }
__device__ __forceinline__ float o2f(int i){ return __int_as_float(i>=0 ? i : (i^0x7FFFFFFF)); }

// ---------------- K0: zero accumulators (runs every replay) ----------------
__global__ void k_init(){
    g_acc[0]=0.0; g_acc[1]=0.0; g_acc[2]=0.0;
    g_cnt=0; g_maxo=(int)0x80000000;
}

// ---------------- K1: per-row pass over the waveform ----------------
// 1 block = 1 row, 256 threads, 1 float4 per thread.
__global__ void __launch_bounds__(256) k_row(const float4* __restrict__ wave,
                                             const float*  __restrict__ depth){
    const int row = blockIdx.x;
    const int t   = threadIdx.x;
    __shared__ float s[NL];
    __shared__ float rw[8], rm[8], r1[8], r2[8];

    float4 v = wave[(size_t)row * 256u + (unsigned)t];
    s[4*t+0]=v.x; s[4*t+1]=v.y; s[4*t+2]=v.z; s[4*t+3]=v.w;

    // Gaussian window accumulation (sigma=5): only warps near t_pos do work.
    const float tpos = __ldg(&depth[row]) * 10.0f;   // (2*d/4000)*20000
    float S1 = 0.0f, S2 = 0.0f;
    {
        float wb = (float)((t & ~31) << 2);          // warp's first element index
        if (tpos > wb - 49.0f && tpos < wb + 176.0f) {
            float j = (float)(t << 2);
            float d0 = j        - tpos;  float e0 = __expf(-0.02f*d0*d0);
            float d1 = j + 1.0f - tpos;  float e1 = __expf(-0.02f*d1*d1);
            float d2 = j + 2.0f - tpos;  float e2 = __expf(-0.02f*d2*d2);
            float d3 = j + 3.0f - tpos;  float e3 = __expf(-0.02f*d3*d3);
            S2 = (e0 + e1) + (e2 + e3);
            S1 = fmaf(v.x*v.x, e0, fmaf(v.y*v.y, e1, fmaf(v.z*v.z, e2, v.w*v.w*e3)));
        }
    }

    float mx = fmaxf(fmaxf(v.x, v.y), fmaxf(v.z, v.w));

    __syncthreads();
    // second difference, boundaries replicate reference exactly
    float lm = (t > 0)   ? s[4*t - 1] : 0.0f;
    float rp = (t < 255) ? s[4*t + 4] : 0.0f;
    float d0 = (t == 0)   ? (v.y - v.x) : (fmaf(-2.0f, v.x, v.y) + lm);
    float d1 = fmaf(-2.0f, v.y, v.z) + v.x;
    float d2 = fmaf(-2.0f, v.z, v.w) + v.y;
    float d3 = (t == 255) ? (v.z - v.w) : (fmaf(-2.0f, v.w, rp) + v.z);

    const float FCT = 9900.0f;   // 1/DT^2 - C^2/DX^2 = 10000 - 100
    float ws;
    {
        float a=FCT*d0, b=FCT*d1, c=FCT*d2, d=FCT*d3;
        ws = fmaf(a,a, fmaf(b,b, fmaf(c,c, d*d)));
    }

    // block reductions: ws,S1,S2 sum; mx max
    #pragma unroll
    for (int o = 16; o > 0; o >>= 1) {
        ws += __shfl_xor_sync(0xFFFFFFFFu, ws, o);
        S1 += __shfl_xor_sync(0xFFFFFFFFu, S1, o);
        S2 += __shfl_xor_sync(0xFFFFFFFFu, S2, o);
        mx  = fmaxf(mx, __shfl_xor_sync(0xFFFFFFFFu, mx, o));
    }
    int lane = t & 31, wid = t >> 5;
    if (lane == 0) { rw[wid]=ws; rm[wid]=mx; r1[wid]=S1; r2[wid]=S2; }
    __syncthreads();
    if (t == 0) {
        float Wt=rw[0], Mt=rm[0], A=r1[0], Bv=r2[0];
        #pragma unroll
        for (int i = 1; i < 8; i++) {
            Wt += rw[i]; Mt = fmaxf(Mt, rm[i]); A += r1[i]; Bv += r2[i];
        }
        g_scr[row] = make_float4(Wt, A / Bv, Mt, 0.0f);
    }
}

// ---------------- K2a: global max over row maxima ----------------
__global__ void __launch_bounds__(256) k_max(){
    const int t = threadIdx.x;
    int i = blockIdx.x * 1024 + t;
    float m =          g_scr[i      ].z;
    m = fmaxf(m,       g_scr[i + 256].z);
    m = fmaxf(m,       g_scr[i + 512].z);
    m = fmaxf(m,       g_scr[i + 768].z);
    #pragma unroll
    for (int o = 16; o > 0; o >>= 1)
        m = fmaxf(m, __shfl_xor_sync(0xFFFFFFFFu, m, o));
    __shared__ float rm[8];
    if ((t & 31) == 0) rm[t >> 5] = m;
    __syncthreads();
    if (t == 0) {
        #pragma unroll
        for (int k = 1; k < 8; k++) m = fmaxf(m, rm[k]);
        atomicMax(&g_maxo, f2o(m));
    }
}

// ---------------- K2b: classification + penalty + global sums ----------------
__global__ void __launch_bounds__(256) k_fin(const float4* __restrict__ logits,
                                             const long long* __restrict__ labels){
    const float gmax = o2f(g_maxo);
    const float inv  = 1.0f / (20.0f * gmax);
    const int t = threadIdx.x;
    double wS = 0.0, cS = 0.0, pS = 0.0; int cnt = 0;

    #pragma unroll
    for (int k = 0; k < 4; k++) {
        int row = blockIdx.x * 1024 + k * 256 + t;
        float4 sc = g_scr[row];
        wS += (double)sc.x;

        float4 lg = logits[row];
        long long lab = labels[row];

        int am = 0; float bm = lg.x;                 // first-occurrence argmax
        if (lg.y > bm) { bm = lg.y; am = 1; }
        if (lg.z > bm) { bm = lg.z; am = 2; }
        if (lg.w > bm) { bm = lg.w; am = 3; }

        float e = sc.y * inv;                         // energies
        float pen;
        if (am >= 2) { float d = 0.1f - e; pen = (e < 0.1f) ? d*d : 0.0f; }
        else         { float d = e - 0.5f; pen = (e > 0.5f) ? d*d : 0.0f; }
        pS += (double)pen;

        if (lab != -1ll) {
            float se = __expf(lg.x - bm) + __expf(lg.y - bm)
                     + __expf(lg.z - bm) + __expf(lg.w - bm);
            float lse = bm + logf(se);
            int li = (int)lab;
            float sel = (li == 0) ? lg.x : (li == 1) ? lg.y : (li == 2) ? lg.z : lg.w;
            cS += (double)(lse - sel);
            cnt++;
        }
    }

    #pragma unroll
    for (int o = 16; o > 0; o >>= 1) {
        wS  += __shfl_xor_sync(0xFFFFFFFFu, wS, o);
        cS  += __shfl_xor_sync(0xFFFFFFFFu, cS, o);
        pS  += __shfl_xor_sync(0xFFFFFFFFu, pS, o);
        cnt += __shfl_xor_sync(0xFFFFFFFFu, cnt, o);
    }
    __shared__ double sw[8], scs[8], sp[8]; __shared__ int sn[8];
    if ((t & 31) == 0) { sw[t>>5]=wS; scs[t>>5]=cS; sp[t>>5]=pS; sn[t>>5]=cnt; }
    __syncthreads();
    if (t == 0) {
        #pragma unroll
        for (int i = 1; i < 8; i++) { wS+=sw[i]; cS+=scs[i]; pS+=sp[i]; cnt+=sn[i]; }
        atomicAdd(&g_acc[0], wS);
        atomicAdd(&g_acc[1], cS);
        atomicAdd(&g_acc[2], pS);
        atomicAdd(&g_cnt, cnt);
    }
}

// ---------------- K3: finalize the 4 outputs ----------------
__global__ void k_out(float* __restrict__ out){
    double wave = g_acc[0] * (1.0 / ((double)NB * (double)NL));
    double cls  = (g_cnt > 0) ? (g_acc[1] / (double)g_cnt) : 0.0;
    double phys = g_acc[2] * (1.0 / (double)NB);
    out[0] = (float)(cls + 0.1 * wave + 0.1 * phys);
    out[1] = (float)cls;
    out[2] = (float)wave;
    out[3] = (float)phys;
}

// ---------------- launch ----------------
extern "C" void kernel_launch(void* const* d_in, const int* in_sizes, int n_in,
                              void* d_out, int out_size){
    const float4*    wave   = (const float4*)d_in[0];   // (65536,1024) f32
    const float4*    logits = (const float4*)d_in[1];   // (65536,4)    f32
    const float*     depth  = (const float*)d_in[2];    // (65536,1)    f32
    const long long* labels = (const long long*)d_in[3];// (65536,)     i64

    k_init<<<1, 1>>>();
    k_row <<<NB, 256>>>(wave, depth);
    k_max <<<64, 256>>>();
    k_fin <<<64, 256>>>(logits, labels);
    k_out <<<1, 1>>>((float*)d_out);
}

// round 2
// speedup vs baseline: 1.9815x; 1.9815x over previous
#include <cuda_runtime.h>

#define NB 65536
#define NL 1024
#define FULLM 0xFFFFFFFFu

// ---------------- device scratch ----------------
__device__ float2 g_we[NB];     // {wave_sq_sum_row, S1/S2 (raw energy)}
__device__ float  g_rmax[NB];   // per-row max
__device__ double g_acc[3];     // [0]=wave sum, [1]=cls nll sum, [2]=penalty sum
__device__ int    g_cnt;
__device__ int    g_maxo;       // global max, ordered-int

__device__ __forceinline__ int   f2o(float f){ int i=__float_as_int(f); return i>=0 ? i : (i^0x7FFFFFFF); }
__device__ __forceinline__ float o2f(int i){ return __int_as_float(i>=0 ? i : (i^0x7FFFFFFF)); }

// ---------------- K0: reset accumulators (every replay) ----------------
__global__ void k_init(){
    g_acc[0]=0.0; g_acc[1]=0.0; g_acc[2]=0.0;
    g_cnt=0; g_maxo=(int)0x80000000;
}

// ---------------- K1: warp-per-row streaming pass ----------------
// block = 256 threads = 8 warps = 8 rows; grid = 8192.
// Thread `lane` loads float4 indices {32*i + lane}, i=0..7 (coalesced, MLP=8).
// Chunk i covers row elements [128*i, 128*i+128); thread holds elems 128i+4*lane..+3.
__global__ void __launch_bounds__(256) k_row(const float4* __restrict__ wave,
                                             const float*  __restrict__ depth){
    const int lane = threadIdx.x & 31;
    const int row  = blockIdx.x * 8 + (threadIdx.x >> 5);
    const float4* rp = wave + (size_t)row * 256u;

    float4 r[8];
    #pragma unroll
    for (int i = 0; i < 8; i++) r[i] = rp[32*i + lane];

    const float tpos = __ldg(&depth[row]) * 10.0f;   // (2*d/4000)*20000

    float ws = 0.0f, S1 = 0.0f, S2 = 0.0f;
    float mx = -3.402823466e+38f;

    #pragma unroll
    for (int i = 0; i < 8; i++) {
        float4 v = r[i];
        mx = fmaxf(mx, fmaxf(fmaxf(v.x, v.y), fmaxf(v.z, v.w)));

        // Gaussian window (sigma = 5): only threads near tpos pay for exp
        float j = (float)(128*i + 4*lane);
        if (fabsf(j + 1.5f - tpos) < 51.5f) {
            float d0 = j        - tpos;  float e0 = __expf(-0.02f*d0*d0);
            float d1 = j + 1.0f - tpos;  float e1 = __expf(-0.02f*d1*d1);
            float d2 = j + 2.0f - tpos;  float e2 = __expf(-0.02f*d2*d2);
            float d3 = j + 3.0f - tpos;  float e3 = __expf(-0.02f*d3*d3);
            S2 += (e0 + e1) + (e2 + e3);
            S1 += fmaf(v.x*v.x, e0, fmaf(v.y*v.y, e1, fmaf(v.z*v.z, e2, v.w*v.w*e3)));
        }

        // neighbors for the second difference
        float lm = __shfl_up_sync  (FULLM, v.w, 1);   // lane-1's last elem
        float rn = __shfl_down_sync(FULLM, v.x, 1);   // lane+1's first elem
        float lmB = (i > 0) ? __shfl_sync(FULLM, r[i-1].w, 31) : 0.0f;
        float rnB = (i < 7) ? __shfl_sync(FULLM, r[i+1].x, 0)  : 0.0f;
        if (lane == 0)  lm = lmB;
        if (lane == 31) rn = rnB;

        float d0 = (i == 0 && lane == 0)  ? (v.y - v.x)
                                          : (fmaf(-2.0f, v.x, v.y) + lm);
        float d1 = fmaf(-2.0f, v.y, v.z) + v.x;
        float d2 = fmaf(-2.0f, v.z, v.w) + v.y;
        float d3 = (i == 7 && lane == 31) ? (v.z - v.w)
                                          : (fmaf(-2.0f, v.w, rn) + v.z);
        ws += fmaf(d0, d0, fmaf(d1, d1, fmaf(d2, d2, d3*d3)));
    }

    // residual factor: (1/DT^2 - C^2/DX^2) = 9900
    ws *= 9900.0f * 9900.0f;

    #pragma unroll
    for (int o = 16; o > 0; o >>= 1) {
        ws += __shfl_xor_sync(FULLM, ws, o);
        S1 += __shfl_xor_sync(FULLM, S1, o);
        S2 += __shfl_xor_sync(FULLM, S2, o);
        mx  = fmaxf(mx, __shfl_xor_sync(FULLM, mx, o));
    }
    if (lane == 0) {
        g_we[row]   = make_float2(ws, S1 / S2);
        g_rmax[row] = mx;
    }
}

// ---------------- K2a: global max over row maxima (dense float4 reads) ----------------
__global__ void __launch_bounds__(256) k_max(){
    const int t = threadIdx.x;
    float4 v = ((const float4*)g_rmax)[blockIdx.x * 256 + t];
    float m = fmaxf(fmaxf(v.x, v.y), fmaxf(v.z, v.w));
    #pragma unroll
    for (int o = 16; o > 0; o >>= 1)
        m = fmaxf(m, __shfl_xor_sync(FULLM, m, o));
    __shared__ float rm[8];
    if ((t & 31) == 0) rm[t >> 5] = m;
    __syncthreads();
    if (t == 0) {
        #pragma unroll
        for (int k = 1; k < 8; k++) m = fmaxf(m, rm[k]);
        atomicMax(&g_maxo, f2o(m));
    }
}

// ---------------- K2b: CE + argmax + penalty + global sums ----------------
__global__ void __launch_bounds__(256) k_fin(const float4* __restrict__ logits,
                                             const long long* __restrict__ labels){
    const float gmax = o2f(g_maxo);
    const float inv  = 1.0f / (20.0f * gmax);
    const int t   = threadIdx.x;
    const int row = blockIdx.x * 256 + t;

    float2 we = g_we[row];
    float4 lg = logits[row];
    long long lab = labels[row];

    double wS = (double)we.x, cS = 0.0, pS;
    int cnt = 0;

    int am = 0; float bm = lg.x;                 // first-occurrence argmax
    if (lg.y > bm) { bm = lg.y; am = 1; }
    if (lg.z > bm) { bm = lg.z; am = 2; }
    if (lg.w > bm) { bm = lg.w; am = 3; }

    float e = we.y * inv;                         // energy
    float pen;
    if (am >= 2) { float d = 0.1f - e; pen = (e < 0.1f) ? d*d : 0.0f; }
    else         { float d = e - 0.5f; pen = (e > 0.5f) ? d*d : 0.0f; }
    pS = (double)pen;

    if (lab != -1ll) {
        float se = __expf(lg.x - bm) + __expf(lg.y - bm)
                 + __expf(lg.z - bm) + __expf(lg.w - bm);
        float lse = bm + logf(se);
        int li = (int)lab;
        float sel = (li == 0) ? lg.x : (li == 1) ? lg.y : (li == 2) ? lg.z : lg.w;
        cS = (double)(lse - sel);
        cnt = 1;
    }

    #pragma unroll
    for (int o = 16; o > 0; o >>= 1) {
        wS  += __shfl_xor_sync(FULLM, wS, o);
        cS  += __shfl_xor_sync(FULLM, cS, o);
        pS  += __shfl_xor_sync(FULLM, pS, o);
        cnt += __shfl_xor_sync(FULLM, cnt, o);
    }
    __shared__ double sw[8], scs[8], sp[8]; __shared__ int sn[8];
    if ((t & 31) == 0) { sw[t>>5]=wS; scs[t>>5]=cS; sp[t>>5]=pS; sn[t>>5]=cnt; }
    __syncthreads();
    if (t == 0) {
        #pragma unroll
        for (int i = 1; i < 8; i++) { wS+=sw[i]; cS+=scs[i]; pS+=sp[i]; cnt+=sn[i]; }
        atomicAdd(&g_acc[0], wS);
        atomicAdd(&g_acc[1], cS);
        atomicAdd(&g_acc[2], pS);
        atomicAdd(&g_cnt, cnt);
    }
}

// ---------------- K3: finalize ----------------
__global__ void k_out(float* __restrict__ out){
    double wave = g_acc[0] * (1.0 / ((double)NB * (double)NL));
    double cls  = (g_cnt > 0) ? (g_acc[1] / (double)g_cnt) : 0.0;
    double phys = g_acc[2] * (1.0 / (double)NB);
    out[0] = (float)(cls + 0.1 * wave + 0.1 * phys);
    out[1] = (float)cls;
    out[2] = (float)wave;
    out[3] = (float)phys;
}

// ---------------- launch ----------------
extern "C" void kernel_launch(void* const* d_in, const int* in_sizes, int n_in,
                              void* d_out, int out_size){
    const float4*    wave   = (const float4*)d_in[0];
    const float4*    logits = (const float4*)d_in[1];
    const float*     depth  = (const float*)d_in[2];
    const long long* labels = (const long long*)d_in[3];

    k_init<<<1, 1>>>();
    k_row <<<NB/8, 256>>>(wave, depth);
    k_max <<<NB/1024, 256>>>();
    k_fin <<<NB/256, 256>>>(logits, labels);
    k_out <<<1, 1>>>((float*)d_out);
}

// round 4
// speedup vs baseline: 2.1603x; 1.0902x over previous
#include <cuda_runtime.h>

#define NB 65536
#define NL 1024
#define FULLM 0xFFFFFFFFu

// ---------------- device scratch (module-initialized; k_out restores state) ----------------
__device__ float  g_e[NB];                        // per-row raw energy S1/S2
__device__ double g_acc[3] = {0.0, 0.0, 0.0};     // [0]=wave, [1]=cls nll, [2]=penalty
__device__ int    g_cnt = 0;                      // n_valid labels
__device__ int    g_maxo = (int)0x80000000;       // global max, ordered-int encoding

__device__ __forceinline__ int   f2o(float f){ int i=__float_as_int(f); return i>=0 ? i : (i^0x7FFFFFFF); }
__device__ __forceinline__ float o2f(int i){ return __int_as_float(i>=0 ? i : (i^0x7FFFFFFF)); }

// ---------------- K1: warp-per-row streaming pass (BW-bound, ~6.3 TB/s) ----------------
// block = 256 threads = 8 warps = 8 rows; grid = 8192.
// Thread `lane` loads float4 indices {32*i + lane}, i=0..7 (coalesced, MLP=8).
__global__ void __launch_bounds__(256) k_row(const float4* __restrict__ wave,
                                             const float*  __restrict__ depth){
    const int lane = threadIdx.x & 31;
    const int wid  = threadIdx.x >> 5;
    const int row  = blockIdx.x * 8 + wid;
    const float4* rp = wave + (size_t)row * 256u;

    float4 r[8];
    #pragma unroll
    for (int i = 0; i < 8; i++) r[i] = rp[32*i + lane];

    const float tpos = __ldg(&depth[row]) * 10.0f;   // (2*d/4000)*20000

    float ws = 0.0f, S1 = 0.0f, S2 = 0.0f;
    float mx = -3.402823466e+38f;

    #pragma unroll
    for (int i = 0; i < 8; i++) {
        float4 v = r[i];
        mx = fmaxf(mx, fmaxf(fmaxf(v.x, v.y), fmaxf(v.z, v.w)));

        // Gaussian window (sigma = 5): only threads near tpos pay for exp
        float j = (float)(128*i + 4*lane);
        if (fabsf(j + 1.5f - tpos) < 51.5f) {
            float d0 = j        - tpos;  float e0 = __expf(-0.02f*d0*d0);
            float d1 = j + 1.0f - tpos;  float e1 = __expf(-0.02f*d1*d1);
            float d2 = j + 2.0f - tpos;  float e2 = __expf(-0.02f*d2*d2);
            float d3 = j + 3.0f - tpos;  float e3 = __expf(-0.02f*d3*d3);
            S2 += (e0 + e1) + (e2 + e3);
            S1 += fmaf(v.x*v.x, e0, fmaf(v.y*v.y, e1, fmaf(v.z*v.z, e2, v.w*v.w*e3)));
        }

        // second difference (boundaries replicate the reference exactly)
        float lm = __shfl_up_sync  (FULLM, v.w, 1);
        float rn = __shfl_down_sync(FULLM, v.x, 1);
        float lmB = (i > 0) ? __shfl_sync(FULLM, r[i-1].w, 31) : 0.0f;
        float rnB = (i < 7) ? __shfl_sync(FULLM, r[i+1].x, 0)  : 0.0f;
        if (lane == 0)  lm = lmB;
        if (lane == 31) rn = rnB;

        float d0 = (i == 0 && lane == 0)  ? (v.y - v.x)
                                          : (fmaf(-2.0f, v.x, v.y) + lm);
        float d1 = fmaf(-2.0f, v.y, v.z) + v.x;
        float d2 = fmaf(-2.0f, v.z, v.w) + v.y;
        float d3 = (i == 7 && lane == 31) ? (v.z - v.w)
                                          : (fmaf(-2.0f, v.w, rn) + v.z);
        ws += fmaf(d0, d0, fmaf(d1, d1, fmaf(d2, d2, d3*d3)));
    }
    ws *= 9900.0f * 9900.0f;   // (1/DT^2 - C^2/DX^2)^2

    #pragma unroll
    for (int o = 16; o > 0; o >>= 1) {
        ws += __shfl_xor_sync(FULLM, ws, o);
        S1 += __shfl_xor_sync(FULLM, S1, o);
        S2 += __shfl_xor_sync(FULLM, S2, o);
        mx  = fmaxf(mx, __shfl_xor_sync(FULLM, mx, o));
    }

    __shared__ float sw[8], sm[8];
    if (lane == 0) {
        g_e[row] = S1 / S2;
        sw[wid] = ws;  sm[wid] = mx;
    }
    __syncthreads();
    if (threadIdx.x == 0) {
        float W = sw[0], M = sm[0];
        #pragma unroll
        for (int i = 1; i < 8; i++) { W += sw[i]; M = fmaxf(M, sm[i]); }
        atomicAdd(&g_acc[0], (double)W);
        atomicMax(&g_maxo, f2o(M));
    }
}

// ---------------- K2: CE + argmax + penalty (4 rows/thread, coalesced) ----------------
__global__ void __launch_bounds__(256) k_fin(const float4* __restrict__ logits,
                                             const longlong2* __restrict__ lab2){
    const int t = blockIdx.x * 256 + threadIdx.x;        // 16384 threads
    const float gmax = o2f(g_maxo);
    const float inv  = 1.0f / (20.0f * gmax);

    float4 e4 = ((const float4*)g_e)[t];                 // rows 4t..4t+3
    const float ev[4] = {e4.x, e4.y, e4.z, e4.w};
    longlong2 la = lab2[2*t], lb = lab2[2*t+1];
    const long long lv[4] = {la.x, la.y, lb.x, lb.y};

    float cS = 0.0f, pS = 0.0f; int cnt = 0;
    #pragma unroll
    for (int k = 0; k < 4; k++) {
        float4 lg = logits[4*t + k];

        int am = 0; float bm = lg.x;                     // first-occurrence argmax
        if (lg.y > bm) { bm = lg.y; am = 1; }
        if (lg.z > bm) { bm = lg.z; am = 2; }
        if (lg.w > bm) { bm = lg.w; am = 3; }

        float e = ev[k] * inv;                           // energy
        if (am >= 2) { float d = 0.1f - e; pS += (e < 0.1f) ? d*d : 0.0f; }
        else         { float d = e - 0.5f; pS += (e > 0.5f) ? d*d : 0.0f; }

        long long lab = lv[k];
        if (lab != -1ll) {
            float se = __expf(lg.x - bm) + __expf(lg.y - bm)
                     + __expf(lg.z - bm) + __expf(lg.w - bm);
            float lse = bm + __logf(se);
            int li = (int)lab;
            float sel = (li == 0) ? lg.x : (li == 1) ? lg.y : (li == 2) ? lg.z : lg.w;
            cS += lse - sel;
            cnt++;
        }
    }

    #pragma unroll
    for (int o = 16; o > 0; o >>= 1) {
        cS  += __shfl_xor_sync(FULLM, cS, o);
        pS  += __shfl_xor_sync(FULLM, pS, o);
        cnt += __shfl_xor_sync(FULLM, cnt, o);
    }
    __shared__ float scs[8], sps[8]; __shared__ int sn[8];
    int lane = threadIdx.x & 31, wid = threadIdx.x >> 5;
    if (lane == 0) { scs[wid]=cS; sps[wid]=pS; sn[wid]=cnt; }
    __syncthreads();
    if (threadIdx.x == 0) {
        #pragma unroll
        for (int i = 1; i < 8; i++) { cS+=scs[i]; pS+=sps[i]; cnt+=sn[i]; }
        atomicAdd(&g_acc[1], (double)cS);
        atomicAdd(&g_acc[2], (double)pS);
        atomicAdd(&g_cnt, cnt);
    }
}

// ---------------- K3: finalize + restore accumulator state for next replay ----------------
__global__ void k_out(float* __restrict__ out){
    double wave = g_acc[0] * (1.0 / ((double)NB * (double)NL));
    double cls  = (g_cnt > 0) ? (g_acc[1] / (double)g_cnt) : 0.0;
    double phys = g_acc[2] * (1.0 / (double)NB);
    out[0] = (float)(cls + 0.1 * wave + 0.1 * phys);
    out[1] = (float)cls;
    out[2] = (float)wave;
    out[3] = (float)phys;
    // reset-after-use: leave globals in their initial state
    g_acc[0] = 0.0; g_acc[1] = 0.0; g_acc[2] = 0.0;
    g_cnt = 0; g_maxo = (int)0x80000000;
}

// ---------------- launch ----------------
extern "C" void kernel_launch(void* const* d_in, const int* in_sizes, int n_in,
                              void* d_out, int out_size){
    const float4* wave   = (const float4*)d_in[0];
    const float4* logits = (const float4*)d_in[1];
    const float*  depth  = (const float*)d_in[2];
    const longlong2* lab = (const longlong2*)d_in[3];

    k_row<<<NB/8, 256>>>(wave, depth);
    k_fin<<<NB/1024, 256>>>(logits, lab);
    k_out<<<1, 1>>>((float*)d_out);
}